// round 5
// baseline (speedup 1.0000x reference)
#include <cuda_runtime.h>
#include <cuda_bf16.h>

// ---------------- problem constants ----------------
#define NN    1000
#define EE    8000
#define FDIM  32
#define W0    32
#define C1 3
#define H1P 499
#define W1C 31
#define C2 6
#define H2P 248
#define W2C 30
#define C3 3
#define H3P 123
#define W3C 29
#define H4P 60
#define W4C 28
#define VLEN 1680

#define NBLK 148
#define NTHR 512
#define NT   (NBLK * NTHR)
#define NWARP (NT / 32)

// ---------------- device scratch (zero-initialized at load) ----------------
__device__ float g_cnt[NN];            // INVARIANT: zero at kernel entry
__device__ float g_hw[NN * FDIM];
__device__ float g_acc[NN * FDIM];     // INVARIANT: zero at kernel entry
__device__ float g_img1[C1 * H1P * W1C];
__device__ float g_img2[C2 * H2P * W2C];
__device__ float g_img3[C3 * H3P * W3C];
__device__ float g_v[VLEN];
__device__ float g_fc1[1024];
__device__ float g_fc2[1024];
__device__ int   g_bar_count;          // barrier arrive counter
__device__ int   g_bar_gen;            // barrier generation

__device__ __forceinline__ float leaky(float v) {
    return v > 0.f ? v : 0.2f * v;
}

// Software grid barrier: safe because grid (148 blocks) <= SM count, so all
// CTAs are co-resident. Generation-based; state persists across graph replays.
__device__ __forceinline__ void grid_sync() {
    __syncthreads();
    if (threadIdx.x == 0) {
        int gen = atomicAdd(&g_bar_gen, 0);      // read gen BEFORE arriving
        __threadfence();                          // publish my stage's writes
        if (atomicAdd(&g_bar_count, 1) == NBLK - 1) {
            g_bar_count = 0;                      // reset for next barrier
            __threadfence();
            atomicAdd(&g_bar_gen, 1);             // release
        } else {
            while (atomicAdd(&g_bar_gen, 0) == gen) { }
        }
    }
    __syncthreads();
}

// warp-per-item edge/self-loop scatter (lane = feature)
__device__ __forceinline__ void scatter_pass(const int* __restrict__ ei,
                                             int warp, int lane) {
    for (int item = warp; item < EE + NN; item += NWARP) {
        if (item < EE) {
            int r = ei[item];
            int c = ei[EE + item];
            float norm = rsqrtf((1.f + __ldcg(&g_cnt[r])) *
                                (1.f + __ldcg(&g_cnt[c])));
            atomicAdd(&g_acc[c * FDIM + lane],
                      __ldcg(&g_hw[r * FDIM + lane]) * norm);
        } else {
            int n = item - EE;
            float inv = 1.f / (1.f + __ldcg(&g_cnt[n]));
            atomicAdd(&g_acc[n * FDIM + lane],
                      __ldcg(&g_hw[n * FDIM + lane]) * inv);
        }
    }
}

__global__ void __launch_bounds__(NTHR, 1) fused_all(
    const float* __restrict__ x,  const int* __restrict__ ei,
    const float* __restrict__ W1, const float* __restrict__ b1,
    const float* __restrict__ W2, const float* __restrict__ b2,
    const float* __restrict__ k1, const float* __restrict__ kb1,
    const float* __restrict__ k2, const float* __restrict__ kb2,
    const float* __restrict__ k3, const float* __restrict__ kb3,
    const float* __restrict__ k4, const float* __restrict__ kb4,
    const float* __restrict__ fw1, const float* __restrict__ fb1,
    const float* __restrict__ fw2, const float* __restrict__ fb2,
    const float* __restrict__ fw3, const float* __restrict__ fb3,
    float* __restrict__ out)
{
    const int t    = blockIdx.x * NTHR + threadIdx.x;
    const int warp = t >> 5;
    const int lane = t & 31;
    __shared__ __align__(16) float sv[VLEN];

    // ---- S1: hw1 = x(:,3:6) @ W1(3:6,:)   +   degree counts (cnt==0 invariant)
    for (int i = t; i < NN * FDIM; i += NT) {
        int n = i >> 5, j = i & 31;
        g_hw[i] = x[n * 6 + 3] * W1[3 * 32 + j]
                + x[n * 6 + 4] * W1[4 * 32 + j]
                + x[n * 6 + 5] * W1[5 * 32 + j];
    }
    for (int e = t; e < EE; e += NT) atomicAdd(&g_cnt[ei[EE + e]], 1.f);
    grid_sync();

    // ---- S2: scatter layer 1 (acc==0 invariant)
    scatter_pass(ei, warp, lane);
    grid_sync();

    // ---- S3: h1 = leaky(acc+b1); hw = h1@W2; zero acc for scatter2
    for (int n = warp; n < NN; n += NWARP) {
        float h = leaky(__ldcg(&g_acc[n * FDIM + lane]) + b1[lane]);
        g_acc[n * FDIM + lane] = 0.f;
        float s = 0.f;
#pragma unroll
        for (int k = 0; k < 32; k++)
            s += __shfl_sync(0xffffffffu, h, k) * W2[k * 32 + lane];
        g_hw[n * FDIM + lane] = s;
    }
    grid_sync();

    // ---- S4: scatter layer 2
    scatter_pass(ei, warp, lane);
    grid_sync();

    // ---- S5: conv1 (input = leaky(acc+b2) inline)  +  re-zero cnt for next call
    for (int idx = t; idx < C1 * H1P * W1C; idx += NT) {
        int w  = idx % W1C;
        int ph = (idx / W1C) % H1P;
        int o  = idx / (W1C * H1P);
        float best = -1e30f;
#pragma unroll
        for (int rr = 0; rr < 2; rr++) {
            int h = 2 * ph + rr;
            float s = kb1[o];
#pragma unroll
            for (int kh = 0; kh < 3; kh++) {
#pragma unroll
                for (int kw = 0; kw < 2; kw++) {
                    int ww = w + kw;
                    float in0 = leaky(__ldcg(&g_acc[(h + kh) * W0 + ww]) + b2[ww]);
                    s += in0 * k1[(o * 3 + kh) * 2 + kw];
                }
            }
            best = fmaxf(best, s);
        }
        g_img1[idx] = fmaxf(best, 0.f);
    }
    for (int i = t; i < NN; i += NT) g_cnt[i] = 0.f;
    grid_sync();

    // ---- S6: conv2  +  re-zero acc for next call
    for (int idx = t; idx < C2 * H2P * W2C; idx += NT) {
        int w  = idx % W2C;
        int ph = (idx / W2C) % H2P;
        int o  = idx / (W2C * H2P);
        float best = -1e30f;
#pragma unroll
        for (int rr = 0; rr < 2; rr++) {
            int h = 2 * ph + rr;
            float s = kb2[o];
#pragma unroll
            for (int i2 = 0; i2 < 3; i2++) {
#pragma unroll
                for (int kh = 0; kh < 3; kh++) {
#pragma unroll
                    for (int kw = 0; kw < 2; kw++) {
                        s += __ldcg(&g_img1[(i2 * H1P + h + kh) * W1C + w + kw]) *
                             k2[((o * 3 + i2) * 3 + kh) * 2 + kw];
                    }
                }
            }
            best = fmaxf(best, s);
        }
        g_img2[idx] = fmaxf(best, 0.f);
    }
    for (int i = t; i < NN * FDIM; i += NT) g_acc[i] = 0.f;
    grid_sync();

    // ---- S7: conv3
    for (int idx = t; idx < C3 * H3P * W3C; idx += NT) {
        int w  = idx % W3C;
        int ph = (idx / W3C) % H3P;
        int o  = idx / (W3C * H3P);
        float best = -1e30f;
#pragma unroll
        for (int rr = 0; rr < 2; rr++) {
            int h = 2 * ph + rr;
            float s = kb3[o];
#pragma unroll
            for (int i2 = 0; i2 < 6; i2++) {
#pragma unroll
                for (int kh = 0; kh < 3; kh++) {
#pragma unroll
                    for (int kw = 0; kw < 2; kw++) {
                        s += __ldcg(&g_img2[(i2 * H2P + h + kh) * W2C + w + kw]) *
                             k3[((o * 6 + i2) * 3 + kh) * 2 + kw];
                    }
                }
            }
            best = fmaxf(best, s);
        }
        g_img3[idx] = fmaxf(best, 0.f);
    }
    grid_sync();

    // ---- S8: conv4 -> v
    for (int idx = t; idx < H4P * W4C; idx += NT) {
        int w  = idx % W4C;
        int ph = idx / W4C;
        float best = -1e30f;
#pragma unroll
        for (int rr = 0; rr < 2; rr++) {
            int h = 2 * ph + rr;
            float s = kb4[0];
#pragma unroll
            for (int i2 = 0; i2 < 3; i2++) {
#pragma unroll
                for (int kh = 0; kh < 3; kh++) {
#pragma unroll
                    for (int kw = 0; kw < 2; kw++) {
                        s += __ldcg(&g_img3[(i2 * H3P + h + kh) * W3C + w + kw]) *
                             k4[(i2 * 3 + kh) * 2 + kw];
                    }
                }
            }
            best = fmaxf(best, s);
        }
        g_v[idx] = fmaxf(best, 0.f);
    }
    grid_sync();

    // ---- S9: FC1  (1024 x 1680), input staged in smem
    for (int k = threadIdx.x; k < VLEN; k += NTHR) sv[k] = __ldcg(&g_v[k]);
    __syncthreads();
    for (int r = warp; r < 1024; r += NWARP) {
        const float4* wr = (const float4*)(fw1 + (long)r * VLEN);
        const float4* s4 = (const float4*)sv;
        float s = 0.f;
        for (int k = lane; k < VLEN / 4; k += 32) {
            float4 a = wr[k], v4 = s4[k];
            s += a.x * v4.x + a.y * v4.y + a.z * v4.z + a.w * v4.w;
        }
#pragma unroll
        for (int off = 16; off > 0; off >>= 1)
            s += __shfl_down_sync(0xffffffffu, s, off);
        if (lane == 0) g_fc1[r] = s + fb1[r];
    }
    grid_sync();

    // ---- S10: FC2  (1024 x 1024)
    for (int k = threadIdx.x; k < 1024; k += NTHR) sv[k] = __ldcg(&g_fc1[k]);
    __syncthreads();
    for (int r = warp; r < 1024; r += NWARP) {
        const float4* wr = (const float4*)(fw2 + (long)r * 1024);
        const float4* s4 = (const float4*)sv;
        float s = 0.f;
        for (int k = lane; k < 1024 / 4; k += 32) {
            float4 a = wr[k], v4 = s4[k];
            s += a.x * v4.x + a.y * v4.y + a.z * v4.z + a.w * v4.w;
        }
#pragma unroll
        for (int off = 16; off > 0; off >>= 1)
            s += __shfl_down_sync(0xffffffffu, s, off);
        if (lane == 0) g_fc2[r] = s + fb2[r];
    }
    grid_sync();

    // ---- S11: FC3  (64 x 1024) -> out
    for (int k = threadIdx.x; k < 1024; k += NTHR) sv[k] = __ldcg(&g_fc2[k]);
    __syncthreads();
    for (int r = warp; r < 64; r += NWARP) {
        const float4* wr = (const float4*)(fw3 + (long)r * 1024);
        const float4* s4 = (const float4*)sv;
        float s = 0.f;
        for (int k = lane; k < 1024 / 4; k += 32) {
            float4 a = wr[k], v4 = s4[k];
            s += a.x * v4.x + a.y * v4.y + a.z * v4.z + a.w * v4.w;
        }
#pragma unroll
        for (int off = 16; off > 0; off >>= 1)
            s += __shfl_down_sync(0xffffffffu, s, off);
        if (lane == 0) out[r] = s + fb3[r];
    }
}

// ---------------- launch ----------------
extern "C" void kernel_launch(void* const* d_in, const int* in_sizes, int n_in,
                              void* d_out, int out_size) {
    const float* x   = (const float*)d_in[0];
    const int*   ei  = (const int*)d_in[1];   // int64 in reference -> int32 here
    const float* W1  = (const float*)d_in[2];
    const float* b1  = (const float*)d_in[3];
    const float* W2  = (const float*)d_in[4];
    const float* b2  = (const float*)d_in[5];
    const float* k1  = (const float*)d_in[6];
    const float* kb1 = (const float*)d_in[7];
    const float* k2  = (const float*)d_in[8];
    const float* kb2 = (const float*)d_in[9];
    const float* k3  = (const float*)d_in[10];
    const float* kb3 = (const float*)d_in[11];
    const float* k4  = (const float*)d_in[12];
    const float* kb4 = (const float*)d_in[13];
    const float* fw1 = (const float*)d_in[14];
    const float* fb1 = (const float*)d_in[15];
    const float* fw2 = (const float*)d_in[16];
    const float* fb2 = (const float*)d_in[17];
    const float* fw3 = (const float*)d_in[18];
    const float* fb3 = (const float*)d_in[19];
    float* out = (float*)d_out;

    fused_all<<<NBLK, NTHR>>>(x, ei, W1, b1, W2, b2, k1, kb1, k2, kb2,
                              k3, kb3, k4, kb4, fw1, fb1, fw2, fb2,
                              fw3, fb3, out);
}

// round 6
// speedup vs baseline: 1.1408x; 1.1408x over previous
#include <cuda_runtime.h>
#include <cuda_bf16.h>

// ---------------- problem constants ----------------
#define NN    1000
#define EE    8000
#define FDIM  32
#define W0    32
#define C1 3
#define H1P 499
#define W1C 31
#define C2 6
#define H2P 248
#define W2C 30
#define C3 3
#define H3P 123
#define W3C 29
#define H4P 60
#define W4C 28
#define VLEN 1680

#define NBLK 148
#define NTHR 512
#define NT   (NBLK * NTHR)
#define NWARP (NT / 32)

// ---------------- device scratch (zero-initialized at load) ----------------
__device__ float g_cnt[NN];            // INVARIANT: zero at kernel entry
__device__ float g_hw[NN * FDIM];
__device__ float g_acc[NN * FDIM];     // INVARIANT: zero at kernel entry
__device__ float g_img1[C1 * H1P * W1C];
__device__ float g_img2[C2 * H2P * W2C];
__device__ float g_img3[C3 * H3P * W3C];
__device__ float g_v[VLEN];
__device__ float g_fc1[1024];
__device__ float g_fc2[1024];
__device__ int            g_bar_count;   // arrivals (atomic)
__device__ volatile int   g_bar_gen;     // release flag (plain volatile ld/st)

__device__ __forceinline__ float leaky(float v) {
    return v > 0.f ? v : 0.2f * v;
}

// Software grid barrier. Safe: grid == 148 == SM count, 1 CTA/SM, all
// co-resident. Arrivals use ONE atomic each; spinners use plain volatile
// LOADS (no atomic-ALU serialization); release is a volatile store.
// 'target' is a per-block monotone counter seeded from g_bar_gen at entry
// (all blocks provably read the same base: release needs all arrivals).
__device__ __forceinline__ void grid_sync(int& target) {
    __syncthreads();
    if (threadIdx.x == 0) {
        __threadfence();                            // publish stage writes (L2)
        if (atomicAdd(&g_bar_count, 1) == NBLK - 1) {
            g_bar_count = 0;                        // safe: all blocks waiting
            __threadfence();
            g_bar_gen = target;                     // release
        } else {
            while (g_bar_gen - target < 0) { }      // load-only spin
        }
    }
    __syncthreads();
    target++;
}

// warp-per-item edge/self-loop scatter (lane = feature)
__device__ __forceinline__ void scatter_pass(const int* __restrict__ ei,
                                             int warp, int lane) {
    for (int item = warp; item < EE + NN; item += NWARP) {
        if (item < EE) {
            int r = ei[item];
            int c = ei[EE + item];
            float cr = 0.f, cc = 0.f;
            if (lane == 0) { cr = __ldcg(&g_cnt[r]); cc = __ldcg(&g_cnt[c]); }
            cr = __shfl_sync(0xffffffffu, cr, 0);
            cc = __shfl_sync(0xffffffffu, cc, 0);
            float norm = rsqrtf((1.f + cr) * (1.f + cc));
            atomicAdd(&g_acc[c * FDIM + lane],
                      __ldcg(&g_hw[r * FDIM + lane]) * norm);
        } else {
            int n = item - EE;
            float cn = 0.f;
            if (lane == 0) cn = __ldcg(&g_cnt[n]);
            cn = __shfl_sync(0xffffffffu, cn, 0);
            float inv = 1.f / (1.f + cn);
            atomicAdd(&g_acc[n * FDIM + lane],
                      __ldcg(&g_hw[n * FDIM + lane]) * inv);
        }
    }
}

__global__ void __launch_bounds__(NTHR, 1) fused_all(
    const float* __restrict__ x,  const int* __restrict__ ei,
    const float* __restrict__ W1, const float* __restrict__ b1,
    const float* __restrict__ W2, const float* __restrict__ b2,
    const float* __restrict__ k1, const float* __restrict__ kb1,
    const float* __restrict__ k2, const float* __restrict__ kb2,
    const float* __restrict__ k3, const float* __restrict__ kb3,
    const float* __restrict__ k4, const float* __restrict__ kb4,
    const float* __restrict__ fw1, const float* __restrict__ fb1,
    const float* __restrict__ fw2, const float* __restrict__ fb2,
    const float* __restrict__ fw3, const float* __restrict__ fb3,
    float* __restrict__ out)
{
    const int t    = blockIdx.x * NTHR + threadIdx.x;
    const int warp = t >> 5;
    const int lane = t & 31;
    __shared__ __align__(16) float sv[VLEN];

    int bar = g_bar_gen + 1;   // barrier generation base (same in all blocks)

    // ---- S1: hw1 = x(:,3:6) @ W1(3:6,:)   +   degree counts (cnt==0 invariant)
    for (int i = t; i < NN * FDIM; i += NT) {
        int n = i >> 5, j = i & 31;
        g_hw[i] = x[n * 6 + 3] * W1[3 * 32 + j]
                + x[n * 6 + 4] * W1[4 * 32 + j]
                + x[n * 6 + 5] * W1[5 * 32 + j];
    }
    for (int e = t; e < EE; e += NT) atomicAdd(&g_cnt[ei[EE + e]], 1.f);
    grid_sync(bar);

    // ---- S2: scatter layer 1 (acc==0 invariant)
    scatter_pass(ei, warp, lane);
    grid_sync(bar);

    // ---- S3: h1 = leaky(acc+b1); hw = h1@W2; zero acc for scatter2
    for (int n = warp; n < NN; n += NWARP) {
        float h = leaky(__ldcg(&g_acc[n * FDIM + lane]) + b1[lane]);
        g_acc[n * FDIM + lane] = 0.f;
        float s = 0.f;
#pragma unroll
        for (int k = 0; k < 32; k++)
            s += __shfl_sync(0xffffffffu, h, k) * W2[k * 32 + lane];
        g_hw[n * FDIM + lane] = s;
    }
    grid_sync(bar);

    // ---- S4: scatter layer 2
    scatter_pass(ei, warp, lane);
    grid_sync(bar);

    // ---- S5: conv1 (input = leaky(acc+b2) inline)  +  re-zero cnt
    for (int idx = t; idx < C1 * H1P * W1C; idx += NT) {
        int w  = idx % W1C;
        int ph = (idx / W1C) % H1P;
        int o  = idx / (W1C * H1P);
        float best = -1e30f;
#pragma unroll
        for (int rr = 0; rr < 2; rr++) {
            int h = 2 * ph + rr;
            float s = kb1[o];
#pragma unroll
            for (int kh = 0; kh < 3; kh++) {
#pragma unroll
                for (int kw = 0; kw < 2; kw++) {
                    int ww = w + kw;
                    float in0 = leaky(__ldcg(&g_acc[(h + kh) * W0 + ww]) + b2[ww]);
                    s += in0 * k1[(o * 3 + kh) * 2 + kw];
                }
            }
            best = fmaxf(best, s);
        }
        g_img1[idx] = fmaxf(best, 0.f);
    }
    for (int i = t; i < NN; i += NT) g_cnt[i] = 0.f;
    grid_sync(bar);

    // ---- S6: conv2  +  re-zero acc
    for (int idx = t; idx < C2 * H2P * W2C; idx += NT) {
        int w  = idx % W2C;
        int ph = (idx / W2C) % H2P;
        int o  = idx / (W2C * H2P);
        float best = -1e30f;
#pragma unroll
        for (int rr = 0; rr < 2; rr++) {
            int h = 2 * ph + rr;
            float s = kb2[o];
#pragma unroll
            for (int i2 = 0; i2 < 3; i2++) {
#pragma unroll
                for (int kh = 0; kh < 3; kh++) {
#pragma unroll
                    for (int kw = 0; kw < 2; kw++) {
                        s += __ldcg(&g_img1[(i2 * H1P + h + kh) * W1C + w + kw]) *
                             k2[((o * 3 + i2) * 3 + kh) * 2 + kw];
                    }
                }
            }
            best = fmaxf(best, s);
        }
        g_img2[idx] = fmaxf(best, 0.f);
    }
    for (int i = t; i < NN * FDIM; i += NT) g_acc[i] = 0.f;
    grid_sync(bar);

    // ---- S7: conv3
    for (int idx = t; idx < C3 * H3P * W3C; idx += NT) {
        int w  = idx % W3C;
        int ph = (idx / W3C) % H3P;
        int o  = idx / (W3C * H3P);
        float best = -1e30f;
#pragma unroll
        for (int rr = 0; rr < 2; rr++) {
            int h = 2 * ph + rr;
            float s = kb3[o];
#pragma unroll
            for (int i2 = 0; i2 < 6; i2++) {
#pragma unroll
                for (int kh = 0; kh < 3; kh++) {
#pragma unroll
                    for (int kw = 0; kw < 2; kw++) {
                        s += __ldcg(&g_img2[(i2 * H2P + h + kh) * W2C + w + kw]) *
                             k3[((o * 6 + i2) * 3 + kh) * 2 + kw];
                    }
                }
            }
            best = fmaxf(best, s);
        }
        g_img3[idx] = fmaxf(best, 0.f);
    }
    grid_sync(bar);

    // ---- S8: conv4 -> v
    for (int idx = t; idx < H4P * W4C; idx += NT) {
        int w  = idx % W4C;
        int ph = idx / W4C;
        float best = -1e30f;
#pragma unroll
        for (int rr = 0; rr < 2; rr++) {
            int h = 2 * ph + rr;
            float s = kb4[0];
#pragma unroll
            for (int i2 = 0; i2 < 3; i2++) {
#pragma unroll
                for (int kh = 0; kh < 3; kh++) {
#pragma unroll
                    for (int kw = 0; kw < 2; kw++) {
                        s += __ldcg(&g_img3[(i2 * H3P + h + kh) * W3C + w + kw]) *
                             k4[(i2 * 3 + kh) * 2 + kw];
                    }
                }
            }
            best = fmaxf(best, s);
        }
        g_v[idx] = fmaxf(best, 0.f);
    }
    grid_sync(bar);

    // ---- S9: FC1  (1024 x 1680), input staged in smem
    for (int k = threadIdx.x; k < VLEN; k += NTHR) sv[k] = __ldcg(&g_v[k]);
    __syncthreads();
    for (int r = warp; r < 1024; r += NWARP) {
        const float4* wr = (const float4*)(fw1 + (long)r * VLEN);
        const float4* s4 = (const float4*)sv;
        float s = 0.f;
        for (int k = lane; k < VLEN / 4; k += 32) {
            float4 a = wr[k], v4 = s4[k];
            s += a.x * v4.x + a.y * v4.y + a.z * v4.z + a.w * v4.w;
        }
#pragma unroll
        for (int off = 16; off > 0; off >>= 1)
            s += __shfl_down_sync(0xffffffffu, s, off);
        if (lane == 0) g_fc1[r] = s + fb1[r];
    }
    grid_sync(bar);

    // ---- S10: FC2  (1024 x 1024)
    for (int k = threadIdx.x; k < 1024; k += NTHR) sv[k] = __ldcg(&g_fc1[k]);
    __syncthreads();
    for (int r = warp; r < 1024; r += NWARP) {
        const float4* wr = (const float4*)(fw2 + (long)r * 1024);
        const float4* s4 = (const float4*)sv;
        float s = 0.f;
        for (int k = lane; k < 1024 / 4; k += 32) {
            float4 a = wr[k], v4 = s4[k];
            s += a.x * v4.x + a.y * v4.y + a.z * v4.z + a.w * v4.w;
        }
#pragma unroll
        for (int off = 16; off > 0; off >>= 1)
            s += __shfl_down_sync(0xffffffffu, s, off);
        if (lane == 0) g_fc2[r] = s + fb2[r];
    }
    grid_sync(bar);

    // ---- S11: FC3  (64 x 1024) -> out
    for (int k = threadIdx.x; k < 1024; k += NTHR) sv[k] = __ldcg(&g_fc2[k]);
    __syncthreads();
    for (int r = warp; r < 64; r += NWARP) {
        const float4* wr = (const float4*)(fw3 + (long)r * 1024);
        const float4* s4 = (const float4*)sv;
        float s = 0.f;
        for (int k = lane; k < 1024 / 4; k += 32) {
            float4 a = wr[k], v4 = s4[k];
            s += a.x * v4.x + a.y * v4.y + a.z * v4.z + a.w * v4.w;
        }
#pragma unroll
        for (int off = 16; off > 0; off >>= 1)
            s += __shfl_down_sync(0xffffffffu, s, off);
        if (lane == 0) out[r] = s + fb3[r];
    }
}

// ---------------- launch ----------------
extern "C" void kernel_launch(void* const* d_in, const int* in_sizes, int n_in,
                              void* d_out, int out_size) {
    const float* x   = (const float*)d_in[0];
    const int*   ei  = (const int*)d_in[1];   // int64 in reference -> int32 here
    const float* W1  = (const float*)d_in[2];
    const float* b1  = (const float*)d_in[3];
    const float* W2  = (const float*)d_in[4];
    const float* b2  = (const float*)d_in[5];
    const float* k1  = (const float*)d_in[6];
    const float* kb1 = (const float*)d_in[7];
    const float* k2  = (const float*)d_in[8];
    const float* kb2 = (const float*)d_in[9];
    const float* k3  = (const float*)d_in[10];
    const float* kb3 = (const float*)d_in[11];
    const float* k4  = (const float*)d_in[12];
    const float* kb4 = (const float*)d_in[13];
    const float* fw1 = (const float*)d_in[14];
    const float* fb1 = (const float*)d_in[15];
    const float* fw2 = (const float*)d_in[16];
    const float* fb2 = (const float*)d_in[17];
    const float* fw3 = (const float*)d_in[18];
    const float* fb3 = (const float*)d_in[19];
    float* out = (float*)d_out;

    fused_all<<<NBLK, NTHR>>>(x, ei, W1, b1, W2, b2, k1, kb1, k2, kb2,
                              k3, kb3, k4, kb4, fw1, fb1, fw2, fb2,
                              fw3, fb3, out);
}

// round 7
// speedup vs baseline: 1.1760x; 1.0309x over previous
#include <cuda_runtime.h>
#include <cuda_bf16.h>

// ---------------- problem constants ----------------
#define NN    1000
#define EE    8000
#define FDIM  32
#define W0    32
#define VLEN  1680            // 60*28

#define NBLK 148
#define NTHR 512
#define NT   (NBLK * NTHR)
#define NWARP (NT / 32)

// conv tail per-block slice sizes (block owns one conv4 pooled row r)
#define IN_ROWS 46            // input rows [16r, 16r+45]
#define C1R 22                // conv1 pooled rows [8r, 8r+21], 31 wide, 3 ch
#define C2R 10                // conv2 pooled rows [4r, 4r+9], 30 wide, 6 ch
#define C3R 4                 // conv3 pooled rows [2r, 2r+3], 29 wide, 3 ch

// ---------------- device scratch (zero-initialized at load) ----------------
__device__ float g_cnt[NN];            // INVARIANT: zero at kernel entry
__device__ float g_hw[NN * FDIM];
__device__ float g_acc[NN * FDIM];     // INVARIANT: zero at kernel entry
__device__ float g_v[VLEN];
__device__ float g_fc1[1024];
__device__ float g_fc2[1024];
__device__ int   g_bar_count;
__device__ int   g_bar_gen;

__device__ __forceinline__ float leaky(float v) {
    return v > 0.f ? v : 0.2f * v;
}

// -------- release/acquire primitives (no full MEMBAR drains) --------
__device__ __forceinline__ int atom_add_release(int* p, int v) {
    int old;
    asm volatile("atom.add.release.gpu.global.s32 %0, [%1], %2;"
                 : "=r"(old) : "l"(p), "r"(v) : "memory");
    return old;
}
__device__ __forceinline__ int ld_acquire(int* p) {
    int v;
    asm volatile("ld.acquire.gpu.global.s32 %0, [%1];"
                 : "=r"(v) : "l"(p) : "memory");
    return v;
}
__device__ __forceinline__ void st_release(int* p, int v) {
    asm volatile("st.release.gpu.global.s32 [%0], %1;"
                 :: "l"(p), "r"(v) : "memory");
}

// Software grid barrier. grid == 148 == SM count -> all CTAs co-resident.
// Arrival: one release-RMW. Spin: acquire LOADS (no atomic-ALU occupancy).
// 'target' seeded from g_bar_gen at entry (all blocks provably read the same
// base: any release requires this block's arrival, which follows its read).
__device__ __forceinline__ void grid_sync(int& target) {
    __syncthreads();
    if (threadIdx.x == 0) {
        if (atom_add_release(&g_bar_count, 1) == NBLK - 1) {
            g_bar_count = 0;                 // ordered before release below
            st_release(&g_bar_gen, target);
        } else {
            while (ld_acquire(&g_bar_gen) - target < 0) { }
        }
    }
    __syncthreads();
    target++;
}

// warp-per-item edge/self-loop scatter (lane = feature)
__device__ __forceinline__ void scatter_pass(const int* __restrict__ ei,
                                             int warp, int lane) {
    for (int item = warp; item < EE + NN; item += NWARP) {
        if (item < EE) {
            int r = ei[item];
            int c = ei[EE + item];
            float cr = 0.f, cc = 0.f;
            if (lane == 0) { cr = __ldcg(&g_cnt[r]); cc = __ldcg(&g_cnt[c]); }
            cr = __shfl_sync(0xffffffffu, cr, 0);
            cc = __shfl_sync(0xffffffffu, cc, 0);
            float norm = rsqrtf((1.f + cr) * (1.f + cc));
            atomicAdd(&g_acc[c * FDIM + lane],
                      __ldcg(&g_hw[r * FDIM + lane]) * norm);
        } else {
            int n = item - EE;
            float cn = 0.f;
            if (lane == 0) cn = __ldcg(&g_cnt[n]);
            cn = __shfl_sync(0xffffffffu, cn, 0);
            float inv = 1.f / (1.f + cn);
            atomicAdd(&g_acc[n * FDIM + lane],
                      __ldcg(&g_hw[n * FDIM + lane]) * inv);
        }
    }
}

__global__ void __launch_bounds__(NTHR, 1) fused_all(
    const float* __restrict__ x,  const int* __restrict__ ei,
    const float* __restrict__ W1, const float* __restrict__ b1,
    const float* __restrict__ W2, const float* __restrict__ b2,
    const float* __restrict__ k1, const float* __restrict__ kb1,
    const float* __restrict__ k2, const float* __restrict__ kb2,
    const float* __restrict__ k3, const float* __restrict__ kb3,
    const float* __restrict__ k4, const float* __restrict__ kb4,
    const float* __restrict__ fw1, const float* __restrict__ fb1,
    const float* __restrict__ fw2, const float* __restrict__ fb2,
    const float* __restrict__ fw3, const float* __restrict__ fb3,
    float* __restrict__ out)
{
    const int t    = blockIdx.x * NTHR + threadIdx.x;
    const int warp = t >> 5;
    const int lane = t & 31;
    const int wib  = threadIdx.x >> 5;     // warp-in-block (0..15)

    // shared pool: conv slice buffers / FC input vector (reused)
    __shared__ __align__(16) float smem_pool[IN_ROWS * 32 + C1R * 31 * 3 +
                                             C2R * 30 * 6 + C3R * 29 * 3];

    int bar = ld_acquire(&g_bar_gen) + 1;  // same base in all blocks

    // ---- S1: hw1 = x(:,3:6) @ W1(3:6,:)  +  degree counts (cnt==0 invariant)
    for (int i = t; i < NN * FDIM; i += NT) {
        int n = i >> 5, j = i & 31;
        g_hw[i] = x[n * 6 + 3] * W1[3 * 32 + j]
                + x[n * 6 + 4] * W1[4 * 32 + j]
                + x[n * 6 + 5] * W1[5 * 32 + j];
    }
    for (int e = t; e < EE; e += NT) atomicAdd(&g_cnt[ei[EE + e]], 1.f);
    grid_sync(bar);

    // ---- S2: scatter layer 1 (acc==0 invariant)
    scatter_pass(ei, warp, lane);
    grid_sync(bar);

    // ---- S3: h1 = leaky(acc+b1); hw = h1@W2; zero acc for scatter2
    for (int n = warp; n < NN; n += NWARP) {
        float h = leaky(__ldcg(&g_acc[n * FDIM + lane]) + b1[lane]);
        g_acc[n * FDIM + lane] = 0.f;
        float s = 0.f;
#pragma unroll
        for (int k = 0; k < 32; k++)
            s += __shfl_sync(0xffffffffu, h, k) * W2[k * 32 + lane];
        g_hw[n * FDIM + lane] = s;
    }
    grid_sync(bar);

    // ---- S4: scatter layer 2
    scatter_pass(ei, warp, lane);
    grid_sync(bar);

    // ---- S5: ENTIRE conv tail, block-local (one conv4 row per block) ------
    if (blockIdx.x < 60) {
        const int r = blockIdx.x;
        float* s_in = smem_pool;                       // [46][32]
        float* s_c1 = s_in + IN_ROWS * 32;             // [3][22][31]
        float* s_c2 = s_c1 + 3 * C1R * 31;             // [6][10][30]
        float* s_c3 = s_c2 + 6 * C2R * 30;             // [3][4][29]

        // input slice: leaky(acc + b2)
        for (int idx = threadIdx.x; idx < IN_ROWS * 32; idx += NTHR) {
            int row = idx >> 5, c = idx & 31;
            s_in[idx] = leaky(__ldcg(&g_acc[(16 * r + row) * 32 + c]) + b2[c]);
        }
        __syncthreads();

        // conv1 + relu + pool  -> s_c1  (3 ch, 22 pooled rows, 31 cols)
        for (int idx = threadIdx.x; idx < 3 * C1R * 31; idx += NTHR) {
            int o = idx / (C1R * 31), rem = idx % (C1R * 31);
            int p = rem / 31, w = rem % 31;
            float best = -1e30f;
#pragma unroll
            for (int rr = 0; rr < 2; rr++) {
                float s = kb1[o];
#pragma unroll
                for (int kh = 0; kh < 3; kh++)
#pragma unroll
                    for (int kw = 0; kw < 2; kw++)
                        s += s_in[(2 * p + rr + kh) * 32 + w + kw] *
                             k1[(o * 3 + kh) * 2 + kw];
                best = fmaxf(best, s);
            }
            s_c1[idx] = fmaxf(best, 0.f);
        }
        __syncthreads();

        // conv2 + relu + pool  -> s_c2  (6 ch, 10 pooled rows, 30 cols)
        for (int idx = threadIdx.x; idx < 6 * C2R * 30; idx += NTHR) {
            int o = idx / (C2R * 30), rem = idx % (C2R * 30);
            int p = rem / 30, w = rem % 30;
            float best = -1e30f;
#pragma unroll
            for (int rr = 0; rr < 2; rr++) {
                float s = kb2[o];
#pragma unroll
                for (int i2 = 0; i2 < 3; i2++)
#pragma unroll
                    for (int kh = 0; kh < 3; kh++)
#pragma unroll
                        for (int kw = 0; kw < 2; kw++)
                            s += s_c1[i2 * (C1R * 31) + (2 * p + rr + kh) * 31 + w + kw] *
                                 k2[((o * 3 + i2) * 3 + kh) * 2 + kw];
                best = fmaxf(best, s);
            }
            s_c2[idx] = fmaxf(best, 0.f);
        }
        __syncthreads();

        // conv3 + relu + pool  -> s_c3  (3 ch, 4 pooled rows, 29 cols)
        for (int idx = threadIdx.x; idx < 3 * C3R * 29; idx += NTHR) {
            int o = idx / (C3R * 29), rem = idx % (C3R * 29);
            int p = rem / 29, w = rem % 29;
            float best = -1e30f;
#pragma unroll
            for (int rr = 0; rr < 2; rr++) {
                float s = kb3[o];
#pragma unroll
                for (int i2 = 0; i2 < 6; i2++)
#pragma unroll
                    for (int kh = 0; kh < 3; kh++)
#pragma unroll
                        for (int kw = 0; kw < 2; kw++)
                            s += s_c2[i2 * (C2R * 30) + (2 * p + rr + kh) * 30 + w + kw] *
                                 k3[((o * 6 + i2) * 3 + kh) * 2 + kw];
                best = fmaxf(best, s);
            }
            s_c3[idx] = fmaxf(best, 0.f);
        }
        __syncthreads();

        // conv4 + relu + pool  -> g_v row r  (28 cols)
        for (int w = threadIdx.x; w < 28; w += NTHR) {
            float best = -1e30f;
#pragma unroll
            for (int rr = 0; rr < 2; rr++) {
                float s = kb4[0];
#pragma unroll
                for (int i2 = 0; i2 < 3; i2++)
#pragma unroll
                    for (int kh = 0; kh < 3; kh++)
#pragma unroll
                        for (int kw = 0; kw < 2; kw++)
                            s += s_c3[i2 * (C3R * 29) + (rr + kh) * 29 + w + kw] *
                                 k4[(i2 * 3 + kh) * 2 + kw];
                best = fmaxf(best, s);
            }
            g_v[r * 28 + w] = fmaxf(best, 0.f);
        }
    } else {
        // idle blocks restore g_cnt invariant for the next call
        for (int i = threadIdx.x + (blockIdx.x - 60) * NTHR; i < NN;
             i += 88 * NTHR)
            g_cnt[i] = 0.f;
    }
    grid_sync(bar);

    // ---- S6: FC1 (1024 x 1680)  +  restore g_acc invariant ----------------
    {
        float* sv = smem_pool;
        for (int k = threadIdx.x; k < VLEN; k += NTHR) sv[k] = __ldcg(&g_v[k]);
        for (int i = t; i < NN * FDIM; i += NT) g_acc[i] = 0.f;
        __syncthreads();
        for (int row = wib * NBLK + blockIdx.x; row < 1024; row += 16 * NBLK) {
            const float4* wr = (const float4*)(fw1 + (long)row * VLEN);
            const float4* s4 = (const float4*)sv;
            float s = 0.f;
            for (int k = lane; k < VLEN / 4; k += 32) {
                float4 a = wr[k], v4 = s4[k];
                s += a.x * v4.x + a.y * v4.y + a.z * v4.z + a.w * v4.w;
            }
#pragma unroll
            for (int off = 16; off > 0; off >>= 1)
                s += __shfl_down_sync(0xffffffffu, s, off);
            if (lane == 0) g_fc1[row] = s + fb1[row];
        }
    }
    grid_sync(bar);

    // ---- S7: FC2 (1024 x 1024) -------------------------------------------
    {
        float* sv = smem_pool;
        for (int k = threadIdx.x; k < 1024; k += NTHR) sv[k] = __ldcg(&g_fc1[k]);
        __syncthreads();
        for (int row = wib * NBLK + blockIdx.x; row < 1024; row += 16 * NBLK) {
            const float4* wr = (const float4*)(fw2 + (long)row * 1024);
            const float4* s4 = (const float4*)sv;
            float s = 0.f;
            for (int k = lane; k < 256; k += 32) {
                float4 a = wr[k], v4 = s4[k];
                s += a.x * v4.x + a.y * v4.y + a.z * v4.z + a.w * v4.w;
            }
#pragma unroll
            for (int off = 16; off > 0; off >>= 1)
                s += __shfl_down_sync(0xffffffffu, s, off);
            if (lane == 0) g_fc2[row] = s + fb2[row];
        }
    }
    grid_sync(bar);

    // ---- S8: FC3 (64 x 1024) -> out --------------------------------------
    {
        float* sv = smem_pool;
        int row = wib * NBLK + blockIdx.x;
        if (row < 64) {
            for (int k = threadIdx.x & 31 ? 0 : 0, kk = lane; kk < 1024; kk += 32)
                sv[kk] = __ldcg(&g_fc2[kk]);   // each active warp loads; cheap
            __syncwarp();
            const float4* wr = (const float4*)(fw3 + (long)row * 1024);
            const float4* s4 = (const float4*)sv;
            float s = 0.f;
            for (int k = lane; k < 256; k += 32) {
                float4 a = wr[k], v4 = s4[k];
                s += a.x * v4.x + a.y * v4.y + a.z * v4.z + a.w * v4.w;
            }
#pragma unroll
            for (int off = 16; off > 0; off >>= 1)
                s += __shfl_down_sync(0xffffffffu, s, off);
            if (lane == 0) out[row] = s + fb3[row];
        }
    }
}

// ---------------- launch ----------------
extern "C" void kernel_launch(void* const* d_in, const int* in_sizes, int n_in,
                              void* d_out, int out_size) {
    const float* x   = (const float*)d_in[0];
    const int*   ei  = (const int*)d_in[1];   // int64 in reference -> int32 here
    const float* W1  = (const float*)d_in[2];
    const float* b1  = (const float*)d_in[3];
    const float* W2  = (const float*)d_in[4];
    const float* b2  = (const float*)d_in[5];
    const float* k1  = (const float*)d_in[6];
    const float* kb1 = (const float*)d_in[7];
    const float* k2  = (const float*)d_in[8];
    const float* kb2 = (const float*)d_in[9];
    const float* k3  = (const float*)d_in[10];
    const float* kb3 = (const float*)d_in[11];
    const float* k4  = (const float*)d_in[12];
    const float* kb4 = (const float*)d_in[13];
    const float* fw1 = (const float*)d_in[14];
    const float* fb1 = (const float*)d_in[15];
    const float* fw2 = (const float*)d_in[16];
    const float* fb2 = (const float*)d_in[17];
    const float* fw3 = (const float*)d_in[18];
    const float* fb3 = (const float*)d_in[19];
    float* out = (float*)d_out;

    fused_all<<<NBLK, NTHR>>>(x, ei, W1, b1, W2, b2, k1, kb1, k2, kb2,
                              k3, kb3, k4, kb4, fw1, fb1, fw2, fb2,
                              fw3, fb3, out);
}

// round 8
// speedup vs baseline: 1.3171x; 1.1199x over previous
#include <cuda_runtime.h>

// ---------------- problem constants ----------------
#define NN    1000
#define EE    8000
#define FDIM  32
#define VLEN  1680            // 60*28

// scatter grid
#define SBLK 148
#define STHR 512
#define SWARP (SBLK * STHR / 32)   // 2368 warps; ceil(9000/2368)=4 items/warp

// conv tail per-block slice sizes (block owns one conv4 pooled row r)
#define IN_ROWS 46
#define C1R 22
#define C2R 10
#define C3R 4

// ---------------- device scratch (zero-initialized at load) ----------------
__device__ float g_cnt[NN];            // INVARIANT: zero at kernel entry (zeroed by k_conv)
__device__ float g_hw[NN * FDIM];      // hw1 = X@W1
__device__ float g_accA[NN * FDIM];    // layer-1 aggregation
__device__ float g_accB[NN * FDIM];    // layer-2 aggregation (pre-W2)
__device__ float g_v[VLEN];
__device__ float g_fc1[1024];
__device__ float g_fc2[1024];

__device__ __forceinline__ float leaky(float v) {
    return v > 0.f ? v : 0.2f * v;
}

// ---- K1: hw1 = x(:,3:6)@W1(3:6,:) ; deg counts ; zero accA/accB ----------
__global__ void k_init(const float* __restrict__ x,
                       const float* __restrict__ W1,
                       const int* __restrict__ ei) {
    int t = blockIdx.x * blockDim.x + threadIdx.x;
    if (t < NN * FDIM) {
        int n = t >> 5, j = t & 31;
        g_hw[t] = x[n * 6 + 3] * W1[3 * 32 + j]
                + x[n * 6 + 4] * W1[4 * 32 + j]
                + x[n * 6 + 5] * W1[5 * 32 + j];
        g_accA[t] = 0.f;
        g_accB[t] = 0.f;
    }
    if (t < EE) atomicAdd(&g_cnt[ei[EE + t]], 1.0f);
}

// ---- K2: scatter layer 1: accA[c] += rsqrt((1+d_r)(1+d_c)) * hw1[r] ------
// items: EE edges then NN self-loops (self: r==c, same norm formula).
__global__ void __launch_bounds__(STHR, 1) k_scat1(const int* __restrict__ ei) {
    int t = blockIdx.x * blockDim.x + threadIdx.x;
    int warp = t >> 5, lane = t & 31;
    float vals[4]; int dsts[4];
#pragma unroll
    for (int u = 0; u < 4; u++) {
        int item = warp + u * SWARP;
        dsts[u] = -1;
        if (item < EE + NN) {
            int r, c;
            if (item < EE) { r = ei[item]; c = ei[EE + item]; }
            else           { r = item - EE; c = r; }
            float cr = g_cnt[r];
            float cc = g_cnt[c];
            float hv = g_hw[r * FDIM + lane];
            vals[u] = hv * rsqrtf((1.f + cr) * (1.f + cc));
            dsts[u] = c;
        }
    }
#pragma unroll
    for (int u = 0; u < 4; u++)
        if (dsts[u] >= 0) atomicAdd(&g_accA[dsts[u] * FDIM + lane], vals[u]);
}

// ---- K3: scatter layer 2: accB[c] += norm * leaky(accA[r] + b1) ----------
// (W2 postponed: Â·(h1@W2) == (Â·h1)@W2, applied in k_conv input stage)
__global__ void __launch_bounds__(STHR, 1) k_scat2(const int* __restrict__ ei,
                                                   const float* __restrict__ b1) {
    int t = blockIdx.x * blockDim.x + threadIdx.x;
    int warp = t >> 5, lane = t & 31;
    float bl = b1[lane];
    float vals[4]; int dsts[4];
#pragma unroll
    for (int u = 0; u < 4; u++) {
        int item = warp + u * SWARP;
        dsts[u] = -1;
        if (item < EE + NN) {
            int r, c;
            if (item < EE) { r = ei[item]; c = ei[EE + item]; }
            else           { r = item - EE; c = r; }
            float cr = g_cnt[r];
            float cc = g_cnt[c];
            float av = g_accA[r * FDIM + lane];
            vals[u] = leaky(av + bl) * rsqrtf((1.f + cr) * (1.f + cc));
            dsts[u] = c;
        }
    }
#pragma unroll
    for (int u = 0; u < 4; u++)
        if (dsts[u] >= 0) atomicAdd(&g_accB[dsts[u] * FDIM + lane], vals[u]);
}

// ---- K4: conv tail, block-local (blocks 0..59); block 60 re-zeros g_cnt --
__global__ void __launch_bounds__(512, 1) k_conv(
    const float* __restrict__ W2, const float* __restrict__ b2,
    const float* __restrict__ k1, const float* __restrict__ kb1,
    const float* __restrict__ k2, const float* __restrict__ kb2,
    const float* __restrict__ k3, const float* __restrict__ kb3,
    const float* __restrict__ k4, const float* __restrict__ kb4) {
    if (blockIdx.x == 60) {
        for (int i = threadIdx.x; i < NN; i += 512) g_cnt[i] = 0.f;
        return;
    }
    const int r = blockIdx.x;
    const int wib  = threadIdx.x >> 5;
    const int lane = threadIdx.x & 31;

    __shared__ __align__(16) float s_w2[FDIM * FDIM];          // [k][c]
    __shared__ __align__(16) float s_in[IN_ROWS * 32];
    __shared__ __align__(16) float s_c1[3 * C1R * 31];
    __shared__ __align__(16) float s_c2[6 * C2R * 30];
    __shared__ __align__(16) float s_c3[3 * C3R * 29];

    for (int i = threadIdx.x; i < FDIM * FDIM; i += 512) s_w2[i] = W2[i];
    __syncthreads();

    // input slice: in[row][c] = leaky( accB[16r+row] @ W2[:,c] + b2[c] )
    for (int row = wib; row < IN_ROWS; row += 16) {
        const float* arow = &g_accB[(16 * r + row) * FDIM];
        float s = b2[lane];
#pragma unroll
        for (int k = 0; k < FDIM; k++)
            s += arow[k] * s_w2[k * FDIM + lane];   // arow[k]: warp broadcast
        s_in[row * 32 + lane] = leaky(s);
    }
    __syncthreads();

    // conv1 + relu + pool
    for (int idx = threadIdx.x; idx < 3 * C1R * 31; idx += 512) {
        int o = idx / (C1R * 31), rem = idx % (C1R * 31);
        int p = rem / 31, w = rem % 31;
        float best = -1e30f;
#pragma unroll
        for (int rr = 0; rr < 2; rr++) {
            float s = kb1[o];
#pragma unroll
            for (int kh = 0; kh < 3; kh++)
#pragma unroll
                for (int kw = 0; kw < 2; kw++)
                    s += s_in[(2 * p + rr + kh) * 32 + w + kw] *
                         k1[(o * 3 + kh) * 2 + kw];
            best = fmaxf(best, s);
        }
        s_c1[idx] = fmaxf(best, 0.f);
    }
    __syncthreads();

    // conv2 + relu + pool
    for (int idx = threadIdx.x; idx < 6 * C2R * 30; idx += 512) {
        int o = idx / (C2R * 30), rem = idx % (C2R * 30);
        int p = rem / 30, w = rem % 30;
        float best = -1e30f;
#pragma unroll
        for (int rr = 0; rr < 2; rr++) {
            float s = kb2[o];
#pragma unroll
            for (int i2 = 0; i2 < 3; i2++)
#pragma unroll
                for (int kh = 0; kh < 3; kh++)
#pragma unroll
                    for (int kw = 0; kw < 2; kw++)
                        s += s_c1[i2 * (C1R * 31) + (2 * p + rr + kh) * 31 + w + kw] *
                             k2[((o * 3 + i2) * 3 + kh) * 2 + kw];
            best = fmaxf(best, s);
        }
        s_c2[idx] = fmaxf(best, 0.f);
    }
    __syncthreads();

    // conv3 + relu + pool
    for (int idx = threadIdx.x; idx < 3 * C3R * 29; idx += 512) {
        int o = idx / (C3R * 29), rem = idx % (C3R * 29);
        int p = rem / 29, w = rem % 29;
        float best = -1e30f;
#pragma unroll
        for (int rr = 0; rr < 2; rr++) {
            float s = kb3[o];
#pragma unroll
            for (int i2 = 0; i2 < 6; i2++)
#pragma unroll
                for (int kh = 0; kh < 3; kh++)
#pragma unroll
                    for (int kw = 0; kw < 2; kw++)
                        s += s_c2[i2 * (C2R * 30) + (2 * p + rr + kh) * 30 + w + kw] *
                             k3[((o * 6 + i2) * 3 + kh) * 2 + kw];
            best = fmaxf(best, s);
        }
        s_c3[idx] = fmaxf(best, 0.f);
    }
    __syncthreads();

    // conv4 + relu + pool -> g_v row r
    for (int w = threadIdx.x; w < 28; w += 512) {
        float best = -1e30f;
#pragma unroll
        for (int rr = 0; rr < 2; rr++) {
            float s = kb4[0];
#pragma unroll
            for (int i2 = 0; i2 < 3; i2++)
#pragma unroll
                for (int kh = 0; kh < 3; kh++)
#pragma unroll
                    for (int kw = 0; kw < 2; kw++)
                        s += s_c3[i2 * (C3R * 29) + (rr + kh) * 29 + w + kw] *
                             k4[(i2 * 3 + kh) * 2 + kw];
            best = fmaxf(best, s);
        }
        g_v[r * 28 + w] = fmaxf(best, 0.f);
    }
}

// ---- FC kernels: warp per output row, input vector staged in smem --------
__global__ void __launch_bounds__(512, 1) k_fc1(const float* __restrict__ W,
                                                const float* __restrict__ b) {
    __shared__ __align__(16) float sv[VLEN];
    for (int k = threadIdx.x; k < VLEN; k += 512) sv[k] = g_v[k];
    __syncthreads();
    int warp = (blockIdx.x * 512 + threadIdx.x) >> 5;
    int lane = threadIdx.x & 31;
    const float4* wr = (const float4*)(W + (long)warp * VLEN);
    const float4* s4 = (const float4*)sv;
    float s = 0.f;
    for (int k = lane; k < VLEN / 4; k += 32) {
        float4 a = wr[k], v4 = s4[k];
        s += a.x * v4.x + a.y * v4.y + a.z * v4.z + a.w * v4.w;
    }
#pragma unroll
    for (int off = 16; off > 0; off >>= 1)
        s += __shfl_down_sync(0xffffffffu, s, off);
    if (lane == 0) g_fc1[warp] = s + b[warp];
}

__global__ void __launch_bounds__(512, 1) k_fc2(const float* __restrict__ W,
                                                const float* __restrict__ b) {
    __shared__ __align__(16) float sv[1024];
    for (int k = threadIdx.x; k < 1024; k += 512) sv[k] = g_fc1[k];
    __syncthreads();
    int warp = (blockIdx.x * 512 + threadIdx.x) >> 5;
    int lane = threadIdx.x & 31;
    const float4* wr = (const float4*)(W + (long)warp * 1024);
    const float4* s4 = (const float4*)sv;
    float s = 0.f;
    for (int k = lane; k < 256; k += 32) {
        float4 a = wr[k], v4 = s4[k];
        s += a.x * v4.x + a.y * v4.y + a.z * v4.z + a.w * v4.w;
    }
#pragma unroll
    for (int off = 16; off > 0; off >>= 1)
        s += __shfl_down_sync(0xffffffffu, s, off);
    if (lane == 0) g_fc2[warp] = s + b[warp];
}

__global__ void __launch_bounds__(1024, 1) k_fc3(const float* __restrict__ W,
                                                 const float* __restrict__ b,
                                                 float* __restrict__ out) {
    __shared__ __align__(16) float sv[1024];
    for (int k = threadIdx.x; k < 1024; k += 1024) sv[k] = g_fc2[k];
    __syncthreads();
    int warp = (blockIdx.x * 1024 + threadIdx.x) >> 5;
    int lane = threadIdx.x & 31;
    const float4* wr = (const float4*)(W + (long)warp * 1024);
    const float4* s4 = (const float4*)sv;
    float s = 0.f;
    for (int k = lane; k < 256; k += 32) {
        float4 a = wr[k], v4 = s4[k];
        s += a.x * v4.x + a.y * v4.y + a.z * v4.z + a.w * v4.w;
    }
#pragma unroll
    for (int off = 16; off > 0; off >>= 1)
        s += __shfl_down_sync(0xffffffffu, s, off);
    if (lane == 0) out[warp] = s + b[warp];
}

// ---------------- launch ----------------
extern "C" void kernel_launch(void* const* d_in, const int* in_sizes, int n_in,
                              void* d_out, int out_size) {
    const float* x   = (const float*)d_in[0];
    const int*   ei  = (const int*)d_in[1];   // int64 in reference -> int32 here
    const float* W1  = (const float*)d_in[2];
    const float* b1  = (const float*)d_in[3];
    const float* W2  = (const float*)d_in[4];
    const float* b2  = (const float*)d_in[5];
    const float* k1  = (const float*)d_in[6];
    const float* kb1 = (const float*)d_in[7];
    const float* k2  = (const float*)d_in[8];
    const float* kb2 = (const float*)d_in[9];
    const float* k3  = (const float*)d_in[10];
    const float* kb3 = (const float*)d_in[11];
    const float* k4  = (const float*)d_in[12];
    const float* kb4 = (const float*)d_in[13];
    const float* fw1 = (const float*)d_in[14];
    const float* fb1 = (const float*)d_in[15];
    const float* fw2 = (const float*)d_in[16];
    const float* fb2 = (const float*)d_in[17];
    const float* fw3 = (const float*)d_in[18];
    const float* fb3 = (const float*)d_in[19];
    float* out = (float*)d_out;

    k_init<<<64, 512>>>(x, W1, ei);                 // 32768 >= 32000 & 8000
    k_scat1<<<SBLK, STHR>>>(ei);
    k_scat2<<<SBLK, STHR>>>(ei, b1);
    k_conv<<<61, 512>>>(W2, b2, k1, kb1, k2, kb2, k3, kb3, k4, kb4);
    k_fc1<<<64, 512>>>(fw1, fb1);                   // 1024 warps = 1024 rows
    k_fc2<<<64, 512>>>(fw2, fb2);
    k_fc3<<<2, 1024>>>(fw3, fb3, out);              // 64 warps = 64 rows
}

// round 9
// speedup vs baseline: 1.3292x; 1.0092x over previous
#include <cuda_runtime.h>

// ---------------- problem constants ----------------
#define NN    1000
#define EE    8000
#define FDIM  32
#define VLEN  1680            // 60*28

// scatter grid
#define SBLK 148
#define STHR 512
#define SWARP (SBLK * STHR / 32)   // 2368 warps; ceil(9000/2368)=4 items/warp

// conv tail per-block slice sizes (block owns one conv4 pooled row r)
#define IN_ROWS 46
#define C1R 22
#define C2R 10
#define C3R 4

// ---------------- device scratch (zero-initialized at load) ----------------
__device__ float g_cnt[NN];            // INVARIANT: zero at kernel entry (zeroed by k_conv)
__device__ float g_hw[NN * FDIM];      // hw1 = X@W1
__device__ float g_accA[NN * FDIM];    // layer-1 aggregation
__device__ float g_accB[NN * FDIM];    // layer-2 aggregation (pre-W2)
__device__ float g_v[VLEN];
__device__ float g_fc1[1024];
__device__ float g_fc2[1024];

__device__ __forceinline__ float leaky(float v) {
    return v > 0.f ? v : 0.2f * v;
}

// ---- K1: hw1 = x(:,3:6)@W1(3:6,:) ; deg counts ; zero accA/accB ----------
__global__ void k_init(const float* __restrict__ x,
                       const float* __restrict__ W1,
                       const int* __restrict__ ei) {
    int t = blockIdx.x * blockDim.x + threadIdx.x;
    if (t < NN * FDIM) {
        int n = t >> 5, j = t & 31;
        g_hw[t] = x[n * 6 + 3] * W1[3 * 32 + j]
                + x[n * 6 + 4] * W1[4 * 32 + j]
                + x[n * 6 + 5] * W1[5 * 32 + j];
        g_accA[t] = 0.f;
        g_accB[t] = 0.f;
    }
    if (t < EE) atomicAdd(&g_cnt[ei[EE + t]], 1.0f);
}

// ---- K2: scatter layer 1: accA[c] += rsqrt((1+d_r)(1+d_c)) * hw1[r] ------
// items: EE edges then NN self-loops (self: r==c, same norm formula).
__global__ void __launch_bounds__(STHR, 1) k_scat1(const int* __restrict__ ei) {
    int t = blockIdx.x * blockDim.x + threadIdx.x;
    int warp = t >> 5, lane = t & 31;
    float vals[4]; int dsts[4];
#pragma unroll
    for (int u = 0; u < 4; u++) {
        int item = warp + u * SWARP;
        dsts[u] = -1;
        if (item < EE + NN) {
            int r, c;
            if (item < EE) { r = ei[item]; c = ei[EE + item]; }
            else           { r = item - EE; c = r; }
            float cr = g_cnt[r];
            float cc = g_cnt[c];
            float hv = g_hw[r * FDIM + lane];
            vals[u] = hv * rsqrtf((1.f + cr) * (1.f + cc));
            dsts[u] = c;
        }
    }
#pragma unroll
    for (int u = 0; u < 4; u++)
        if (dsts[u] >= 0) atomicAdd(&g_accA[dsts[u] * FDIM + lane], vals[u]);
}

// ---- K3: scatter layer 2: accB[c] += norm * leaky(accA[r] + b1) ----------
// (W2 postponed: Â·(h1@W2) == (Â·h1)@W2, applied in k_conv input stage)
__global__ void __launch_bounds__(STHR, 1) k_scat2(const int* __restrict__ ei,
                                                   const float* __restrict__ b1) {
    int t = blockIdx.x * blockDim.x + threadIdx.x;
    int warp = t >> 5, lane = t & 31;
    float bl = b1[lane];
    float vals[4]; int dsts[4];
#pragma unroll
    for (int u = 0; u < 4; u++) {
        int item = warp + u * SWARP;
        dsts[u] = -1;
        if (item < EE + NN) {
            int r, c;
            if (item < EE) { r = ei[item]; c = ei[EE + item]; }
            else           { r = item - EE; c = r; }
            float cr = g_cnt[r];
            float cc = g_cnt[c];
            float av = g_accA[r * FDIM + lane];
            vals[u] = leaky(av + bl) * rsqrtf((1.f + cr) * (1.f + cc));
            dsts[u] = c;
        }
    }
#pragma unroll
    for (int u = 0; u < 4; u++)
        if (dsts[u] >= 0) atomicAdd(&g_accB[dsts[u] * FDIM + lane], vals[u]);
}

// ---- K4: conv tail, block-local (blocks 0..59); block 60 re-zeros g_cnt --
__global__ void __launch_bounds__(512, 1) k_conv(
    const float* __restrict__ W2, const float* __restrict__ b2,
    const float* __restrict__ k1, const float* __restrict__ kb1,
    const float* __restrict__ k2, const float* __restrict__ kb2,
    const float* __restrict__ k3, const float* __restrict__ kb3,
    const float* __restrict__ k4, const float* __restrict__ kb4) {
    if (blockIdx.x == 60) {
        for (int i = threadIdx.x; i < NN; i += 512) g_cnt[i] = 0.f;
        return;
    }
    const int r = blockIdx.x;
    const int wib  = threadIdx.x >> 5;
    const int lane = threadIdx.x & 31;

    __shared__ __align__(16) float s_w2[FDIM * FDIM];          // [k][c]
    __shared__ __align__(16) float s_in[IN_ROWS * 32];
    __shared__ __align__(16) float s_c1[3 * C1R * 31];
    __shared__ __align__(16) float s_c2[6 * C2R * 30];
    __shared__ __align__(16) float s_c3[3 * C3R * 29];

    for (int i = threadIdx.x; i < FDIM * FDIM; i += 512) s_w2[i] = W2[i];
    __syncthreads();

    // input slice: in[row][c] = leaky( accB[16r+row] @ W2[:,c] + b2[c] )
    for (int row = wib; row < IN_ROWS; row += 16) {
        const float* arow = &g_accB[(16 * r + row) * FDIM];
        float s = b2[lane];
#pragma unroll
        for (int k = 0; k < FDIM; k++)
            s += arow[k] * s_w2[k * FDIM + lane];   // arow[k]: warp broadcast
        s_in[row * 32 + lane] = leaky(s);
    }
    __syncthreads();

    // conv1 + relu + pool
    for (int idx = threadIdx.x; idx < 3 * C1R * 31; idx += 512) {
        int o = idx / (C1R * 31), rem = idx % (C1R * 31);
        int p = rem / 31, w = rem % 31;
        float best = -1e30f;
#pragma unroll
        for (int rr = 0; rr < 2; rr++) {
            float s = kb1[o];
#pragma unroll
            for (int kh = 0; kh < 3; kh++)
#pragma unroll
                for (int kw = 0; kw < 2; kw++)
                    s += s_in[(2 * p + rr + kh) * 32 + w + kw] *
                         k1[(o * 3 + kh) * 2 + kw];
            best = fmaxf(best, s);
        }
        s_c1[idx] = fmaxf(best, 0.f);
    }
    __syncthreads();

    // conv2 + relu + pool
    for (int idx = threadIdx.x; idx < 6 * C2R * 30; idx += 512) {
        int o = idx / (C2R * 30), rem = idx % (C2R * 30);
        int p = rem / 30, w = rem % 30;
        float best = -1e30f;
#pragma unroll
        for (int rr = 0; rr < 2; rr++) {
            float s = kb2[o];
#pragma unroll
            for (int i2 = 0; i2 < 3; i2++)
#pragma unroll
                for (int kh = 0; kh < 3; kh++)
#pragma unroll
                    for (int kw = 0; kw < 2; kw++)
                        s += s_c1[i2 * (C1R * 31) + (2 * p + rr + kh) * 31 + w + kw] *
                             k2[((o * 3 + i2) * 3 + kh) * 2 + kw];
            best = fmaxf(best, s);
        }
        s_c2[idx] = fmaxf(best, 0.f);
    }
    __syncthreads();

    // conv3 + relu + pool
    for (int idx = threadIdx.x; idx < 3 * C3R * 29; idx += 512) {
        int o = idx / (C3R * 29), rem = idx % (C3R * 29);
        int p = rem / 29, w = rem % 29;
        float best = -1e30f;
#pragma unroll
        for (int rr = 0; rr < 2; rr++) {
            float s = kb3[o];
#pragma unroll
            for (int i2 = 0; i2 < 6; i2++)
#pragma unroll
                for (int kh = 0; kh < 3; kh++)
#pragma unroll
                    for (int kw = 0; kw < 2; kw++)
                        s += s_c2[i2 * (C2R * 30) + (2 * p + rr + kh) * 30 + w + kw] *
                             k3[((o * 6 + i2) * 3 + kh) * 2 + kw];
            best = fmaxf(best, s);
        }
        s_c3[idx] = fmaxf(best, 0.f);
    }
    __syncthreads();

    // conv4 + relu + pool -> g_v row r
    for (int w = threadIdx.x; w < 28; w += 512) {
        float best = -1e30f;
#pragma unroll
        for (int rr = 0; rr < 2; rr++) {
            float s = kb4[0];
#pragma unroll
            for (int i2 = 0; i2 < 3; i2++)
#pragma unroll
                for (int kh = 0; kh < 3; kh++)
#pragma unroll
                    for (int kw = 0; kw < 2; kw++)
                        s += s_c3[i2 * (C3R * 29) + (rr + kh) * 29 + w + kw] *
                             k4[(i2 * 3 + kh) * 2 + kw];
            best = fmaxf(best, s);
        }
        g_v[r * 28 + w] = fmaxf(best, 0.f);
    }
}

// ---- FC kernels: warp per output row, input vector staged in smem --------
__global__ void __launch_bounds__(512, 1) k_fc1(const float* __restrict__ W,
                                                const float* __restrict__ b) {
    __shared__ __align__(16) float sv[VLEN];
    for (int k = threadIdx.x; k < VLEN; k += 512) sv[k] = g_v[k];
    __syncthreads();
    int warp = (blockIdx.x * 512 + threadIdx.x) >> 5;
    int lane = threadIdx.x & 31;
    const float4* wr = (const float4*)(W + (long)warp * VLEN);
    const float4* s4 = (const float4*)sv;
    float s = 0.f;
    for (int k = lane; k < VLEN / 4; k += 32) {
        float4 a = wr[k], v4 = s4[k];
        s += a.x * v4.x + a.y * v4.y + a.z * v4.z + a.w * v4.w;
    }
#pragma unroll
    for (int off = 16; off > 0; off >>= 1)
        s += __shfl_down_sync(0xffffffffu, s, off);
    if (lane == 0) g_fc1[warp] = s + b[warp];
}

__global__ void __launch_bounds__(512, 1) k_fc2(const float* __restrict__ W,
                                                const float* __restrict__ b) {
    __shared__ __align__(16) float sv[1024];
    for (int k = threadIdx.x; k < 1024; k += 512) sv[k] = g_fc1[k];
    __syncthreads();
    int warp = (blockIdx.x * 512 + threadIdx.x) >> 5;
    int lane = threadIdx.x & 31;
    const float4* wr = (const float4*)(W + (long)warp * 1024);
    const float4* s4 = (const float4*)sv;
    float s = 0.f;
    for (int k = lane; k < 256; k += 32) {
        float4 a = wr[k], v4 = s4[k];
        s += a.x * v4.x + a.y * v4.y + a.z * v4.z + a.w * v4.w;
    }
#pragma unroll
    for (int off = 16; off > 0; off >>= 1)
        s += __shfl_down_sync(0xffffffffu, s, off);
    if (lane == 0) g_fc2[warp] = s + b[warp];
}

__global__ void __launch_bounds__(1024, 1) k_fc3(const float* __restrict__ W,
                                                 const float* __restrict__ b,
                                                 float* __restrict__ out) {
    __shared__ __align__(16) float sv[1024];
    for (int k = threadIdx.x; k < 1024; k += 1024) sv[k] = g_fc2[k];
    __syncthreads();
    int warp = (blockIdx.x * 1024 + threadIdx.x) >> 5;
    int lane = threadIdx.x & 31;
    const float4* wr = (const float4*)(W + (long)warp * 1024);
    const float4* s4 = (const float4*)sv;
    float s = 0.f;
    for (int k = lane; k < 256; k += 32) {
        float4 a = wr[k], v4 = s4[k];
        s += a.x * v4.x + a.y * v4.y + a.z * v4.z + a.w * v4.w;
    }
#pragma unroll
    for (int off = 16; off > 0; off >>= 1)
        s += __shfl_down_sync(0xffffffffu, s, off);
    if (lane == 0) out[warp] = s + b[warp];
}

// ---------------- launch ----------------
extern "C" void kernel_launch(void* const* d_in, const int* in_sizes, int n_in,
                              void* d_out, int out_size) {
    const float* x   = (const float*)d_in[0];
    const int*   ei  = (const int*)d_in[1];   // int64 in reference -> int32 here
    const float* W1  = (const float*)d_in[2];
    const float* b1  = (const float*)d_in[3];
    const float* W2  = (const float*)d_in[4];
    const float* b2  = (const float*)d_in[5];
    const float* k1  = (const float*)d_in[6];
    const float* kb1 = (const float*)d_in[7];
    const float* k2  = (const float*)d_in[8];
    const float* kb2 = (const float*)d_in[9];
    const float* k3  = (const float*)d_in[10];
    const float* kb3 = (const float*)d_in[11];
    const float* k4  = (const float*)d_in[12];
    const float* kb4 = (const float*)d_in[13];
    const float* fw1 = (const float*)d_in[14];
    const float* fb1 = (const float*)d_in[15];
    const float* fw2 = (const float*)d_in[16];
    const float* fb2 = (const float*)d_in[17];
    const float* fw3 = (const float*)d_in[18];
    const float* fb3 = (const float*)d_in[19];
    float* out = (float*)d_out;

    k_init<<<64, 512>>>(x, W1, ei);                 // 32768 >= 32000 & 8000
    k_scat1<<<SBLK, STHR>>>(ei);
    k_scat2<<<SBLK, STHR>>>(ei, b1);
    k_conv<<<61, 512>>>(W2, b2, k1, kb1, k2, kb2, k3, kb3, k4, kb4);
    k_fc1<<<64, 512>>>(fw1, fb1);                   // 1024 warps = 1024 rows
    k_fc2<<<64, 512>>>(fw2, fb2);
    k_fc3<<<2, 1024>>>(fw3, fb3, out);              // 64 warps = 64 rows
}